// round 12
// baseline (speedup 1.0000x reference)
#include <cuda_runtime.h>

// CommNet forward: B=8192, N=64, D=128, O=16
//   H1 = tanh(wH1*obs); C1 = (sum_n H1 - H1)/(N-1)
//   H2 = tanh(wH2*H1 + wC2*C1) + obs ; out = H2 @ w_out + b_out
//
// One CTA per batch element, 256 threads.
// Phase: thread = (feature d, agent-half); x[32] in regs (low footprint),
//        per-feature sum combined via 1KB smem psum exchange.
// GEMV: 8 warps = d-eighths; lane = (agent-octet p, o-quad q); per d:
//        2 h-LDS.128 (natural u64 agent pairs) + 1 w-LDS.128 -> 16 FFMA2.
// 8-way d-reduction via quad-swizzled smem partials overlaid on the tile.

#define N_AG 64
#define DIM  128
#define OUTD 16
#define PITCH 68   // floats; 17 16B-units (odd) -> conflict-free row-strided 128b ops

typedef unsigned long long u64;

__device__ __forceinline__ float tanh_fast(float x) {
    float y; asm("tanh.approx.f32 %0, %1;" : "=f"(y) : "f"(x)); return y;
}
__device__ __forceinline__ u64 pack2(float lo, float hi) {
    u64 r; asm("mov.b64 %0, {%1, %2};" : "=l"(r) : "f"(lo), "f"(hi)); return r;
}
__device__ __forceinline__ void unpack2(u64 v, float& lo, float& hi) {
    asm("mov.b64 {%0, %1}, %2;" : "=f"(lo), "=f"(hi) : "l"(v));
}
__device__ __forceinline__ void ffma2(u64& d, u64 a, u64 b) {
    asm("fma.rn.f32x2 %0, %1, %2, %0;" : "+l"(d) : "l"(a), "l"(b));
}

__global__ __launch_bounds__(256, 3)
void commnet_kernel(const float* __restrict__ obs,
                    const float* __restrict__ wH1,
                    const float* __restrict__ wH2,
                    const float* __restrict__ wC2,
                    const float* __restrict__ wout,
                    const float* __restrict__ bout,
                    float* __restrict__ out)
{
    // sh: h2 tile [128][68] floats (34,816 B); after GEMV reused as
    //     partials part[8 dg][64 n][16 o] floats (32,768 B).
    __shared__ __align__(16) float sh[DIM * PITCH];
    __shared__ __align__(16) float wsm[DIM * OUTD];   // 8 KB
    __shared__ float bsm[OUTD];
    __shared__ float psum[2][DIM];                    // 1 KB: half-sums

    const int tid = threadIdx.x;                      // 0..255
    const int b   = blockIdx.x;

    // ---- stage w_out / b_out ----
    {
        const float4* w4  = (const float4*)wout;
        float4*       ws4 = (float4*)wsm;
        #pragma unroll
        for (int i = 0; i < 2; i++)
            ws4[i * 256 + tid] = w4[i * 256 + tid];
        if (tid < OUTD) bsm[tid] = bout[tid];
    }

    // ---- phase setup: d = tid&127, half = tid>>7; x[32] in registers ----
    const int d    = tid & 127;
    const int half = tid >> 7;
    const float* ob = obs + (size_t)b * (N_AG * DIM) + (half * 32) * DIM + d;

    float x[32];
    #pragma unroll
    for (int n = 0; n < 32; n++)
        x[n] = ob[n * DIM];

    const float a1 = wH1[d];
    const float a2 = wH2[d];
    const float c2 = wC2[d];

    // ---- pass 1: half-sum of tanh; combine across halves via smem ----
    float hsum = 0.0f;
    #pragma unroll
    for (int n = 0; n < 32; n++)
        hsum += tanh_fast(a1 * x[n]);
    psum[half][d] = hsum;
    __syncthreads();
    const float sum = psum[0][d] + psum[1][d];
    const float inv = 1.0f / (float)(N_AG - 1);

    // ---- pass 2: h2 per chunk of 4 agents -> tile row d, STS.128 ----
    {
        float* row = &sh[d * PITCH + half * 32];
        #pragma unroll
        for (int m = 0; m < 8; m++) {
            float h2v[4];
            #pragma unroll
            for (int e = 0; e < 4; e++) {
                float xv = x[4 * m + e];
                float h1 = tanh_fast(a1 * xv);
                h2v[e] = tanh_fast(a2 * h1 + c2 * (sum - h1) * inv) + xv;
            }
            *(float4*)&row[4 * m] = make_float4(h2v[0], h2v[1], h2v[2], h2v[3]);
        }
    }
    __syncthreads();

    // ---- GEMV: warp wd = d-eighth (16 d); lane = (p agent-octet, q o-quad) ----
    const int wd = tid >> 5;               // 0..7
    const int p  = (tid >> 2) & 7;
    const int q  = tid & 3;

    u64 acc[4][4];                         // [agent-pair ap][o]; pairs natural
    #pragma unroll
    for (int ap = 0; ap < 4; ap++)
        #pragma unroll
        for (int o = 0; o < 4; o++) acc[ap][o] = 0ull;

    #pragma unroll 4
    for (int i = 0; i < 16; i++) {
        const int dd = 16 * wd + i;
        const ulonglong2* hp = (const ulonglong2*)&sh[dd * PITCH + 8 * p];
        ulonglong2 h01 = hp[0];            // agents (8p,8p+1),(8p+2,8p+3)
        ulonglong2 h23 = hp[1];            // agents (8p+4,8p+5),(8p+6,8p+7)
        float4 wq = *(const float4*)&wsm[dd * OUTD + 4 * q];
        u64 w0 = pack2(wq.x, wq.x);
        u64 w1 = pack2(wq.y, wq.y);
        u64 w2 = pack2(wq.z, wq.z);
        u64 w3 = pack2(wq.w, wq.w);

        ffma2(acc[0][0], h01.x, w0); ffma2(acc[0][1], h01.x, w1);
        ffma2(acc[0][2], h01.x, w2); ffma2(acc[0][3], h01.x, w3);
        ffma2(acc[1][0], h01.y, w0); ffma2(acc[1][1], h01.y, w1);
        ffma2(acc[1][2], h01.y, w2); ffma2(acc[1][3], h01.y, w3);
        ffma2(acc[2][0], h23.x, w0); ffma2(acc[2][1], h23.x, w1);
        ffma2(acc[2][2], h23.x, w2); ffma2(acc[2][3], h23.x, w3);
        ffma2(acc[3][0], h23.y, w0); ffma2(acc[3][1], h23.y, w1);
        ffma2(acc[3][2], h23.y, w2); ffma2(acc[3][3], h23.y, w3);
    }
    __syncthreads();                       // all tile reads complete

    // ---- partials: part[wd][n][16], quad-column swizzle c = q ^ (p&3) ----
    {
        float* part = sh;
        const int c4 = 4 * (q ^ (p & 3));
        #pragma unroll
        for (int ap = 0; ap < 4; ap++) {
            float l0, h0, l1, h1, l2, h2, l3, h3;
            unpack2(acc[ap][0], l0, h0);
            unpack2(acc[ap][1], l1, h1);
            unpack2(acc[ap][2], l2, h2);
            unpack2(acc[ap][3], l3, h3);
            const int n0 = 8 * p + 2 * ap;
            *(float4*)&part[wd * 1024 + n0 * 16 + c4]       = make_float4(l0, l1, l2, l3);
            *(float4*)&part[wd * 1024 + (n0 + 1) * 16 + c4] = make_float4(h0, h1, h2, h3);
        }
    }
    __syncthreads();

    // ---- combine + store: thread t -> agent n = t>>2, o-quad j = t&3 ----
    {
        const float* part = sh;
        const int n   = tid >> 2;
        const int j   = tid & 3;
        const int pn3 = (n >> 3) & 3;
        const int c4  = 4 * (j ^ pn3);            // physical column

        float4 r = *(const float4*)&bsm[4 * j];
        #pragma unroll
        for (int wp = 0; wp < 8; wp++) {
            float4 s = *(const float4*)&part[wp * 1024 + n * 16 + c4];
            r.x += s.x; r.y += s.y; r.z += s.z; r.w += s.w;
        }
        *(float4*)&out[(size_t)b * (N_AG * OUTD) + n * OUTD + 4 * j] = r;
    }
}

extern "C" void kernel_launch(void* const* d_in, const int* in_sizes, int n_in,
                              void* d_out, int out_size) {
    const float* obs  = (const float*)d_in[0];
    const float* wH1  = (const float*)d_in[1];
    // d_in[2] = w_C1: multiplies C0 = 0 -> unused
    const float* wH2  = (const float*)d_in[3];
    const float* wC2  = (const float*)d_in[4];
    const float* wout = (const float*)d_in[5];
    const float* bout = (const float*)d_in[6];
    float* out = (float*)d_out;

    int B = in_sizes[0] / (N_AG * DIM);   // 8192
    commnet_kernel<<<B, 256>>>(obs, wH1, wH2, wC2, wout, bout, out);
}

// round 13
// speedup vs baseline: 1.1617x; 1.1617x over previous
#include <cuda_runtime.h>
#include <cuda_fp16.h>

// CommNet forward: B=8192, N=64, D=128, O=16
//   H1 = tanh(wH1*obs); C1 = (sum_n H1 - H1)/(N-1)
//   H2 = tanh(wH2*H1 + wC2*C1) + obs ; out = H2 @ w_out + b_out
//
// One CTA per batch element, 128 threads.
// Phase: thread = feature d; obs column read ONCE into x[64]; h1 cached as
//   half2[32] (pass2 arg is linear in h1 -> 2 tanh/elem total, not 3).
// GEMV: thread = (d-group g=tid>>4 of 16 d, agent-octet p, o-half oh);
//   per d: 32 B h (2 LDS.128, natural u64 agent pairs) + 32 B w -> 32 FFMA2
//   (2 B/FFMA2). acc = 32 u64.
// Reduction: per-thread contiguous 68-float partial blocks (bank-floor
//   4-way on write and read), 8-way combine, coalesced STG.

#define N_AG 64
#define DIM  128
#define OUTD 16
#define PITCH 68   // floats; odd multiple of 4 -> conflict-free row-strided 128b ops

typedef unsigned long long u64;

__device__ __forceinline__ float tanh_fast(float x) {
    float y; asm("tanh.approx.f32 %0, %1;" : "=f"(y) : "f"(x)); return y;
}
__device__ __forceinline__ u64 pack2(float lo, float hi) {
    u64 r; asm("mov.b64 %0, {%1, %2};" : "=l"(r) : "f"(lo), "f"(hi)); return r;
}
__device__ __forceinline__ void unpack2(u64 v, float& lo, float& hi) {
    asm("mov.b64 {%0, %1}, %2;" : "=f"(lo), "=f"(hi) : "l"(v));
}
__device__ __forceinline__ void ffma2(u64& d, u64 a, u64 b) {
    asm("fma.rn.f32x2 %0, %1, %2, %0;" : "+l"(d) : "l"(a), "l"(b));
}

__global__ __launch_bounds__(128, 4)
void commnet_kernel(const float* __restrict__ obs,
                    const float* __restrict__ wH1,
                    const float* __restrict__ wH2,
                    const float* __restrict__ wC2,
                    const float* __restrict__ wout,
                    const float* __restrict__ bout,
                    float* __restrict__ out)
{
    // sh: h2 tile [128][68] floats (34,816 B); after GEMV reused as
    //     per-thread partial blocks: 128 threads x 68 floats (64 used).
    __shared__ __align__(16) float sh[DIM * PITCH];
    __shared__ __align__(16) float wsm[DIM * OUTD];   // 8 KB
    __shared__ float bsm[OUTD];

    const int tid = threadIdx.x;                      // = feature d for phase
    const int b   = blockIdx.x;

    // ---- stage w_out / b_out ----
    {
        const float4* w4  = (const float4*)wout;
        float4*       ws4 = (float4*)wsm;
        #pragma unroll
        for (int i = 0; i < 4; i++)
            ws4[i * 128 + tid] = w4[i * 128 + tid];
        if (tid < OUTD) bsm[tid] = bout[tid];
    }

    // ---- obs column d=tid into registers: 64 coalesced LDG.32 (read ONCE) ----
    const float* ob = obs + (size_t)b * (N_AG * DIM) + tid;
    float x[N_AG];
    #pragma unroll
    for (int n = 0; n < N_AG; n++)
        x[n] = ob[n * DIM];

    const float a1 = wH1[tid];
    const float a2 = wH2[tid];
    const float c2 = wC2[tid];

    // ---- pass 1: h1 = tanh(a1*x); cache as half2; accumulate sum ----
    half2 h1h[N_AG / 2];
    float sum = 0.0f;
    #pragma unroll
    for (int k = 0; k < N_AG / 2; k++) {
        float ha = tanh_fast(a1 * x[2 * k]);
        float hb = tanh_fast(a1 * x[2 * k + 1]);
        sum += ha + hb;
        h1h[k] = __floats2half2_rn(ha, hb);
    }
    const float inv   = 1.0f / (float)(N_AG - 1);
    const float alpha = a2 - c2 * inv;      // arg = alpha*h1 + beta
    const float beta  = c2 * inv * sum;

    // ---- pass 2: h2 = tanh(alpha*h1 + beta) + x -> tile row d, STS.128 ----
    {
        float* row = &sh[tid * PITCH];
        #pragma unroll
        for (int m = 0; m < 16; m++) {
            float h2v[4];
            #pragma unroll
            for (int e = 0; e < 2; e++) {
                float2 f = __half22float2(h1h[2 * m + e]);
                h2v[2 * e + 0] = tanh_fast(alpha * f.x + beta) + x[4 * m + 2 * e + 0];
                h2v[2 * e + 1] = tanh_fast(alpha * f.y + beta) + x[4 * m + 2 * e + 1];
            }
            *(float4*)&row[4 * m] = make_float4(h2v[0], h2v[1], h2v[2], h2v[3]);
        }
    }
    __syncthreads();

    // ---- GEMV: g = d-group (16 d), p = agent-octet, oh = o-half ----
    const int g  = tid >> 4;               // 0..7
    const int s  = tid & 15;
    const int p  = s >> 1;                 // 0..7: agents 8p..8p+7
    const int oh = s & 1;                  // 0..1: outputs 8oh..8oh+7

    u64 acc[4][8];                         // [agent-pair ap][o-local]
    #pragma unroll
    for (int ap = 0; ap < 4; ap++)
        #pragma unroll
        for (int o = 0; o < 8; o++) acc[ap][o] = 0ull;

    #pragma unroll 2
    for (int i = 0; i < 16; i++) {
        const int d = 16 * g + i;
        const ulonglong2* hp = (const ulonglong2*)&sh[d * PITCH + 8 * p];
        ulonglong2 hA = hp[0];             // agents (8p,8p+1),(8p+2,8p+3)
        ulonglong2 hB = hp[1];             // agents (8p+4,8p+5),(8p+6,8p+7)
        const float4* wp = (const float4*)&wsm[d * OUTD + 8 * oh];
        float4 wq0 = wp[0];
        float4 wq1 = wp[1];
        float wf[8] = {wq0.x, wq0.y, wq0.z, wq0.w, wq1.x, wq1.y, wq1.z, wq1.w};
        u64 h0 = hA.x, h1v = hA.y, h2v = hB.x, h3v = hB.y;
        #pragma unroll
        for (int o = 0; o < 8; o++) {
            u64 wd = pack2(wf[o], wf[o]);
            ffma2(acc[0][o], h0,  wd);
            ffma2(acc[1][o], h1v, wd);
            ffma2(acc[2][o], h2v, wd);
            ffma2(acc[3][o], h3v, wd);
        }
    }
    __syncthreads();                       // all tile reads complete

    // ---- partials: per-thread contiguous block blk[8 agents][8 o] ----
    {
        float* blk = &sh[tid * PITCH];     // pitch 68: 4-way bank floor
        #pragma unroll
        for (int ap = 0; ap < 4; ap++) {
            float l0, u0, l1, u1, l2, u2, l3, u3;
            float l4, u4, l5, u5, l6, u6, l7, u7;
            unpack2(acc[ap][0], l0, u0); unpack2(acc[ap][1], l1, u1);
            unpack2(acc[ap][2], l2, u2); unpack2(acc[ap][3], l3, u3);
            unpack2(acc[ap][4], l4, u4); unpack2(acc[ap][5], l5, u5);
            unpack2(acc[ap][6], l6, u6); unpack2(acc[ap][7], l7, u7);
            float* r0 = &blk[(2 * ap) * 8];        // agent 8p+2ap
            float* r1 = &blk[(2 * ap + 1) * 8];    // agent 8p+2ap+1
            *(float4*)&r0[0] = make_float4(l0, l1, l2, l3);
            *(float4*)&r0[4] = make_float4(l4, l5, l6, l7);
            *(float4*)&r1[0] = make_float4(u0, u1, u2, u3);
            *(float4*)&r1[4] = make_float4(u4, u5, u6, u7);
        }
    }
    __syncthreads();

    // ---- combine + store: thread t -> agent n = t>>1, o-half hh = t&1 ----
    {
        const int n  = tid >> 1;
        const int hh = tid & 1;
        const int sub = (n >> 3) * 2 + hh;         // writer (p, oh) slot
        const int aoff = (n & 7) * 8;              // agent-local row in block

        float4 r0 = *(const float4*)&bsm[8 * hh + 0];
        float4 r1 = *(const float4*)&bsm[8 * hh + 4];
        #pragma unroll
        for (int gp = 0; gp < 8; gp++) {
            const float* blk = &sh[(gp * 16 + sub) * PITCH + aoff];
            float4 s0 = *(const float4*)&blk[0];
            float4 s1 = *(const float4*)&blk[4];
            r0.x += s0.x; r0.y += s0.y; r0.z += s0.z; r0.w += s0.w;
            r1.x += s1.x; r1.y += s1.y; r1.z += s1.z; r1.w += s1.w;
        }
        float* op = out + (size_t)b * (N_AG * OUTD) + n * OUTD + 8 * hh;
        *(float4*)&op[0] = r0;
        *(float4*)&op[4] = r1;
    }
}

extern "C" void kernel_launch(void* const* d_in, const int* in_sizes, int n_in,
                              void* d_out, int out_size) {
    const float* obs  = (const float*)d_in[0];
    const float* wH1  = (const float*)d_in[1];
    // d_in[2] = w_C1: multiplies C0 = 0 -> unused
    const float* wH2  = (const float*)d_in[3];
    const float* wC2  = (const float*)d_in[4];
    const float* wout = (const float*)d_in[5];
    const float* bout = (const float*)d_in[6];
    float* out = (float*)d_out;

    int B = in_sizes[0] / (N_AG * DIM);   // 8192
    commnet_kernel<<<B, 128>>>(obs, wH1, wH2, wC2, wout, bout, out);
}

// round 14
// speedup vs baseline: 1.5812x; 1.3611x over previous
#include <cuda_runtime.h>
#include <cuda_fp16.h>

// CommNet forward: B=8192, N=64, D=128, O=16
//   H1 = tanh(wH1*obs); C1 = (sum_n H1 - H1)/(N-1)
//   H2 = tanh(wH2*H1 + wC2*C1) + obs ; out = H2 @ w_out + b_out
//
// One CTA per batch element, 128 threads (4 warps).
// Phase (R13-proven): thread = feature d; x[64] regs; h1 cached half2;
//   pass2 arg linear in h1 -> 2 tanh/elem. Writes fp32 tile [agent][d]
//   (PITCHW=136) via conflict-free scalar column STS.
// GEMV via tensor cores: mma.m16n8k16 f16->f32. M=o(16), N=agents, K=d(128).
//   A = w^T: batch-invariant fragments staged once in smem, then register-
//   resident (32 regs). B = h tile, read ONCE as LDS.64 pairs + cvt to f16x2.
//   K-reduction internal to MMA: no smem partials, single __syncthreads.

#define N_AG 64
#define DIM  128
#define OUTD 16
#define PITCHW 136   // fp32 words per agent row (128 + 8 pad -> optimal LDS.64)

__device__ __forceinline__ float tanh_fast(float x) {
    float y; asm("tanh.approx.f32 %0, %1;" : "=f"(y) : "f"(x)); return y;
}
// pack (lo, hi) floats -> f16x2 register
__device__ __forceinline__ unsigned cvt_h2(float lo, float hi) {
    unsigned r;
    asm("cvt.rn.f16x2.f32 %0, %1, %2;" : "=r"(r) : "f"(hi), "f"(lo));
    return r;
}
__device__ __forceinline__ void mma16816(
    float& c0, float& c1, float& c2, float& c3,
    unsigned a0, unsigned a1, unsigned a2, unsigned a3,
    unsigned b0, unsigned b1)
{
    asm volatile(
        "mma.sync.aligned.m16n8k16.row.col.f32.f16.f16.f32 "
        "{%0,%1,%2,%3}, {%4,%5,%6,%7}, {%8,%9}, {%0,%1,%2,%3};"
        : "+f"(c0), "+f"(c1), "+f"(c2), "+f"(c3)
        : "r"(a0), "r"(a1), "r"(a2), "r"(a3), "r"(b0), "r"(b1));
}

__global__ __launch_bounds__(128, 4)
void commnet_kernel(const float* __restrict__ obs,
                    const float* __restrict__ wH1,
                    const float* __restrict__ wH2,
                    const float* __restrict__ wC2,
                    const float* __restrict__ wout,
                    const float* __restrict__ bout,
                    float* __restrict__ out)
{
    __shared__ __align__(16) float    sh[N_AG * PITCHW];   // 34,816 B h2 tile
    __shared__ __align__(16) unsigned wfrag[8 * 32 * 4];   //  4,096 B A-frags

    const int tid = threadIdx.x;                 // = feature d for phase
    const int b   = blockIdx.x;

    // ---- stage A-fragments of w^T (frag-order; 2 slots per thread) ----
    // slot (s, l): g = l>>2, tig = l&3; A[o][d] = w[d][o]
    //   a0 = (w[16s+2tig][g],    w[16s+2tig+1][g])
    //   a1 = (w[16s+2tig][g+8],  w[16s+2tig+1][g+8])
    //   a2 = (w[16s+2tig+8][g],  w[16s+2tig+9][g])
    //   a3 = (w[16s+2tig+8][g+8],w[16s+2tig+9][g+8])
    {
        const int s  = tid >> 4;
        const int l0 = (tid & 15) * 2;
        #pragma unroll
        for (int e = 0; e < 2; e++) {
            const int l = l0 + e;
            const int g = l >> 2, tg = l & 3;
            const int d0 = 16 * s + 2 * tg;
            uint4 v;
            v.x = cvt_h2(wout[d0 * OUTD + g],           wout[(d0 + 1) * OUTD + g]);
            v.y = cvt_h2(wout[d0 * OUTD + g + 8],       wout[(d0 + 1) * OUTD + g + 8]);
            v.z = cvt_h2(wout[(d0 + 8) * OUTD + g],     wout[(d0 + 9) * OUTD + g]);
            v.w = cvt_h2(wout[(d0 + 8) * OUTD + g + 8], wout[(d0 + 9) * OUTD + g + 8]);
            *(uint4*)&wfrag[(s * 32 + l) * 4] = v;
        }
    }

    // ---- obs column d=tid into registers: 64 coalesced LDG.32 (read ONCE) ----
    const float* ob = obs + (size_t)b * (N_AG * DIM) + tid;
    float x[N_AG];
    #pragma unroll
    for (int n = 0; n < N_AG; n++)
        x[n] = ob[n * DIM];

    const float a1c = wH1[tid];
    const float a2c = wH2[tid];
    const float c2c = wC2[tid];

    // ---- pass 1: h1 = tanh(a1*x); cache half2; accumulate sum ----
    half2 h1h[N_AG / 2];
    float sum = 0.0f;
    #pragma unroll
    for (int k = 0; k < N_AG / 2; k++) {
        float ha = tanh_fast(a1c * x[2 * k]);
        float hb = tanh_fast(a1c * x[2 * k + 1]);
        sum += ha + hb;
        h1h[k] = __floats2half2_rn(ha, hb);
    }
    const float inv   = 1.0f / (float)(N_AG - 1);
    const float alpha = a2c - c2c * inv;         // arg = alpha*h1 + beta
    const float beta  = c2c * inv * sum;

    // ---- pass 2: h2 -> tile COLUMN d (scalar STS.32, conflict-free) ----
    #pragma unroll
    for (int k = 0; k < N_AG / 2; k++) {
        float2 f = __half22float2(h1h[k]);
        float h2a = tanh_fast(alpha * f.x + beta) + x[2 * k];
        float h2b = tanh_fast(alpha * f.y + beta) + x[2 * k + 1];
        sh[(2 * k) * PITCHW + tid]     = h2a;
        sh[(2 * k + 1) * PITCHW + tid] = h2b;
    }
    __syncthreads();

    // ---- tensor-core GEMV: warp = 16 agents (2 n-tiles), K=128 in 8 steps ----
    const int wid  = tid >> 5;
    const int lane = tid & 31;
    const int g    = lane >> 2;                  // 0..7
    const int tg   = lane & 3;                   // 0..3

    unsigned af[8][4];
    #pragma unroll
    for (int s = 0; s < 8; s++) {
        uint4 v = *(const uint4*)&wfrag[(s * 32 + lane) * 4];
        af[s][0] = v.x; af[s][1] = v.y; af[s][2] = v.z; af[s][3] = v.w;
    }
    const float bg  = bout[g];
    const float bg8 = bout[g + 8];

    float* op = out + (size_t)b * (N_AG * OUTD);

    #pragma unroll
    for (int nt = 0; nt < 2; nt++) {
        const int abase = wid * 16 + nt * 8;     // 8 agents per n-tile
        float c0 = bg, c1 = bg, c2 = bg8, c3 = bg8;
        // B-frag source: h[abase+g][*] row, k-cols 2tg(+1) and +8(+9)
        const float* hb = &sh[(abase + g) * PITCHW + 2 * tg];
        #pragma unroll
        for (int s = 0; s < 8; s++) {
            float2 f0 = *(const float2*)&hb[16 * s];       // k = 16s+2tg, +1
            float2 f1 = *(const float2*)&hb[16 * s + 8];   // k = +8, +9
            unsigned b0 = cvt_h2(f0.x, f0.y);
            unsigned b1 = cvt_h2(f1.x, f1.y);
            mma16816(c0, c1, c2, c3,
                     af[s][0], af[s][1], af[s][2], af[s][3], b0, b1);
        }
        // D[o][agent]: c0=(g, 2tg) c1=(g, 2tg+1) c2=(g+8, 2tg) c3=(g+8, 2tg+1)
        op[(abase + 2 * tg) * OUTD + g]         = c0;
        op[(abase + 2 * tg + 1) * OUTD + g]     = c1;
        op[(abase + 2 * tg) * OUTD + g + 8]     = c2;
        op[(abase + 2 * tg + 1) * OUTD + g + 8] = c3;
    }
}

extern "C" void kernel_launch(void* const* d_in, const int* in_sizes, int n_in,
                              void* d_out, int out_size) {
    const float* obs  = (const float*)d_in[0];
    const float* wH1  = (const float*)d_in[1];
    // d_in[2] = w_C1: multiplies C0 = 0 -> unused
    const float* wH2  = (const float*)d_in[3];
    const float* wC2  = (const float*)d_in[4];
    const float* wout = (const float*)d_in[5];
    const float* bout = (const float*)d_in[6];
    float* out = (float*)d_out;

    int B = in_sizes[0] / (N_AG * DIM);   // 8192
    commnet_kernel<<<B, 128>>>(obs, wH1, wH2, wC2, wout, bout, out);
}